// round 12
// baseline (speedup 1.0000x reference)
#include <cuda_runtime.h>

#define HID 64
typedef unsigned long long u64;

__device__ __forceinline__ u64 pk2(float lo, float hi) {
    u64 r; asm("mov.b64 %0, {%1,%2};" : "=l"(r) : "f"(lo), "f"(hi)); return r;
}
__device__ __forceinline__ void upk2(u64 v, float& lo, float& hi) {
    asm("mov.b64 {%0,%1}, %2;" : "=f"(lo), "=f"(hi) : "l"(v));
}
__device__ __forceinline__ u64 ffma2(u64 a, u64 b, u64 c) {
    u64 d; asm("fma.rn.f32x2 %0, %1, %2, %3;" : "=l"(d) : "l"(a), "l"(b), "l"(c)); return d;
}
__device__ __forceinline__ u64 fmul2(u64 a, u64 b) {
    u64 d; asm("mul.rn.f32x2 %0, %1, %2;" : "=l"(d) : "l"(a), "l"(b)); return d;
}

__global__ void zero_kernel(float* __restrict__ out, int n) {
    int i = blockIdx.x * blockDim.x + threadIdx.x;
    if (i < n) out[i] = 0.0f;
}

// EDGE-PAIR packed scheme, 9 deferred-attr accumulators, DUPLICATED weights.
// smem: per h (64 rows, 16-u64 / 128B stride), each weight stored as (w,w):
//   [0,DIN) : W1[s][h] dup;  DIN : b1[h] dup;  (DIN, DIN+9] : W2[h][m] dup
// Mainloop loads ulonglong2 (LDS.128 -> two dup weights, .x/.y are ready
// FFMA2 operands, no re-pack movs). Each thread carries NP edge-pairs:
// layer-1 = 3(6) FFMA2/pair, layer-2 = 9 FFMA2/pair. Attr applied in epilogue.
template<int DIN, int NP>
__device__ __forceinline__ void run_family(
    const float* __restrict__ x,
    const int*   __restrict__ edges,
    const float* __restrict__ attr,
    const float* __restrict__ W1, const float* __restrict__ b1,
    const float* __restrict__ W2, const float* __restrict__ b2,
    float* __restrict__ out, int E, int blk, int nblk, u64* smem)
{
    constexpr int EPT = 2 * NP;
    u64* sWB = smem;              // [64 * 16] dup weights
    u64* sB2 = sWB + 64 * 16;     // [9] dup b2

    for (int idx = threadIdx.x; idx < 64 * 16; idx += blockDim.x) {
        int h = idx >> 4, s = idx & 15;
        float w = 0.0f;
        if (s < DIN)           w = W1[s * HID + h];
        else if (s == DIN)     w = b1[h];
        else if (s <= DIN + 9) w = W2[h * 9 + (s - DIN - 1)];
        sWB[idx] = pk2(w, w);
    }
    if (threadIdx.x < 9) { float w = b2[threadIdx.x]; sB2[threadIdx.x] = pk2(w, w); }
    __syncthreads();

    const int tid    = blk * (int)blockDim.x + (int)threadIdx.x;
    const int stride = nblk * (int)blockDim.x;

    u64  dd[NP][DIN];      // MLP inputs packed across edge pair
    u64  acc[NP][9];       // mobility accumulators packed across edge pair
    int  tgt[EPT];
    bool valid[EPT];

    #pragma unroll
    for (int p = 0; p < NP; p++) {
        float dv[2][DIN];
        #pragma unroll
        for (int s = 0; s < 2; s++) {
            int k = 2 * p + s;
            int e = tid + k * stride;
            valid[k] = (e < E);
            int ee = valid[k] ? e : 0;
            int i;
            if (DIN == 3) {
                int j = edges[ee];
                i = edges[E + ee];
                dv[s][0] = x[3*j+0] - x[3*i+0];
                dv[s][1] = x[3*j+1] - x[3*i+1];
                dv[s][2] = x[3*j+2] - x[3*i+2];
            } else {
                int j  = edges[ee];
                int kk = edges[E + ee];
                i = edges[2*E + ee];
                float xk0 = x[3*kk+0], xk1 = x[3*kk+1], xk2 = x[3*kk+2];
                dv[s][0] = xk0 - x[3*j+0];
                dv[s][1] = xk1 - x[3*j+1];
                dv[s][2] = xk2 - x[3*j+2];
                dv[s][3] = x[3*i+0] - xk0;
                dv[s][4] = x[3*i+1] - xk1;
                dv[s][5] = x[3*i+2] - xk2;
            }
            tgt[k] = i;
        }
        #pragma unroll
        for (int q = 0; q < DIN; q++) dd[p][q] = pk2(dv[0][q], dv[1][q]);
        #pragma unroll
        for (int m = 0; m < 9; m++) acc[p][m] = sB2[m];
    }

    // Mainloop: 64 h iterations; 7 (DIN3) / 8 (DIN6) LDS.128 per h,
    // 16 FFMA2-class ops per pair per h.
    #pragma unroll 2
    for (int h = 0; h < 64; h++) {
        const ulonglong2* wv = (const ulonglong2*)(sWB + h * 16);
        u64 hv[NP];

        if (DIN == 3) {
            ulonglong2 qa = wv[0];   // w1_0 dup, w1_1 dup
            ulonglong2 qb = wv[1];   // w1_2 dup, b1 dup
            #pragma unroll
            for (int p = 0; p < NP; p++) {
                u64 t = ffma2(dd[p][0], qa.x, qb.y);
                t = ffma2(dd[p][1], qa.y, t);
                t = ffma2(dd[p][2], qb.x, t);
                float lo, hi; upk2(t, lo, hi);
                hv[p] = pk2(fmaxf(lo, 0.0f), fmaxf(hi, 0.0f));
            }
            #pragma unroll
            for (int g = 0; g < 5; g++) {
                ulonglong2 q = wv[2 + g];   // w2_{2g} dup, w2_{2g+1} dup
                #pragma unroll
                for (int p = 0; p < NP; p++)
                    acc[p][2*g+0] = ffma2(hv[p], q.x, acc[p][2*g+0]);
                if (g < 4) {
                    #pragma unroll
                    for (int p = 0; p < NP; p++)
                        acc[p][2*g+1] = ffma2(hv[p], q.y, acc[p][2*g+1]);
                }
            }
        } else {
            ulonglong2 qa = wv[0];   // w1_0, w1_1
            ulonglong2 qb = wv[1];   // w1_2, w1_3
            ulonglong2 qc = wv[2];   // w1_4, w1_5
            ulonglong2 qd = wv[3];   // b1, w2_0
            #pragma unroll
            for (int p = 0; p < NP; p++) {
                u64 t = ffma2(dd[p][0], qa.x, qd.x);
                t = ffma2(dd[p][1], qa.y, t);
                t = ffma2(dd[p][2], qb.x, t);
                t = ffma2(dd[p][3], qb.y, t);
                t = ffma2(dd[p][4], qc.x, t);
                t = ffma2(dd[p][5], qc.y, t);
                float lo, hi; upk2(t, lo, hi);
                hv[p] = pk2(fmaxf(lo, 0.0f), fmaxf(hi, 0.0f));
            }
            #pragma unroll
            for (int p = 0; p < NP; p++)
                acc[p][0] = ffma2(hv[p], qd.y, acc[p][0]);
            #pragma unroll
            for (int g = 0; g < 4; g++) {
                ulonglong2 q = wv[4 + g];   // w2_{2g+1} dup, w2_{2g+2} dup
                #pragma unroll
                for (int p = 0; p < NP; p++)
                    acc[p][2*g+1] = ffma2(hv[p], q.x, acc[p][2*g+1]);
                #pragma unroll
                for (int p = 0; p < NP; p++)
                    acc[p][2*g+2] = ffma2(hv[p], q.y, acc[p][2*g+2]);
            }
        }
    }

    // Epilogue: packed matvec with attr pairs, scatter-add.
    #pragma unroll
    for (int p = 0; p < NP; p++) {
        int e0 = tid + (2*p+0) * stride;
        int e1 = tid + (2*p+1) * stride;
        int ee0 = valid[2*p+0] ? e0 : 0;
        int ee1 = valid[2*p+1] ? e1 : 0;
        u64 atp[3];
        #pragma unroll
        for (int m = 0; m < 3; m++) atp[m] = pk2(attr[3*ee0+m], attr[3*ee1+m]);
        #pragma unroll
        for (int i = 0; i < 3; i++) {
            u64 t = fmul2(acc[p][3*i+2], atp[2]);
            t = ffma2(acc[p][3*i+1], atp[1], t);
            t = ffma2(acc[p][3*i+0], atp[0], t);
            float ylo, yhi; upk2(t, ylo, yhi);
            if (valid[2*p+0]) atomicAdd(&out[3*tgt[2*p+0] + i], ylo);
            if (valid[2*p+1]) atomicAdd(&out[3*tgt[2*p+1] + i], yhi);
        }
    }
}

#define NP3B 2   // DIN=3: 2 pairs = 4 edges/thread
#define NP6B 1   // DIN=6: 1 pair = 2 edges/thread (fused reg budget)

__global__ __launch_bounds__(128, 6)
void fused_hignn_kernel(
    const float* __restrict__ x,
    const int* __restrict__ e2, const float* __restrict__ a2,
    const float* __restrict__ W1_2b, const float* __restrict__ b1_2b,
    const float* __restrict__ W2_2b, const float* __restrict__ b2_2b,
    const int* __restrict__ e3, const float* __restrict__ a3,
    const float* __restrict__ W1_3b, const float* __restrict__ b1_3b,
    const float* __restrict__ W2_3b, const float* __restrict__ b2_3b,
    const int* __restrict__ es, const float* __restrict__ as,
    const float* __restrict__ W1_s, const float* __restrict__ b1_s,
    const float* __restrict__ W2_s, const float* __restrict__ b2_s,
    float* __restrict__ out,
    int E2, int E3, int ES, int B2, int B3, int BS)
{
    __shared__ __align__(16) u64 smem[64 * 16 + 9];
    int b = blockIdx.x;
    if (b < B2) {
        run_family<3, NP3B>(x, e2, a2, W1_2b, b1_2b, W2_2b, b2_2b, out, E2, b, B2, smem);
    } else if (b < B2 + B3) {
        run_family<6, NP6B>(x, e3, a3, W1_3b, b1_3b, W2_3b, b2_3b, out, E3, b - B2, B3, smem);
    } else {
        run_family<3, NP3B>(x, es, as, W1_s, b1_s, W2_s, b2_s, out, ES, b - B2 - B3, BS, smem);
    }
}

extern "C" void kernel_launch(void* const* d_in, const int* in_sizes, int n_in,
                              void* d_out, int out_size)
{
    const float* x   = (const float*)d_in[0];
    const int*   e2  = (const int*)  d_in[1];
    const int*   e3  = (const int*)  d_in[2];
    const int*   es  = (const int*)  d_in[3];
    const float* a2  = (const float*)d_in[5];
    const float* a3  = (const float*)d_in[6];
    const float* as  = (const float*)d_in[7];
    const float* W1_2b = (const float*)d_in[9];
    const float* b1_2b = (const float*)d_in[10];
    const float* W2_2b = (const float*)d_in[11];
    const float* b2_2b = (const float*)d_in[12];
    const float* W1_3b = (const float*)d_in[13];
    const float* b1_3b = (const float*)d_in[14];
    const float* W2_3b = (const float*)d_in[15];
    const float* b2_3b = (const float*)d_in[16];
    const float* W1_s  = (const float*)d_in[17];
    const float* b1_s  = (const float*)d_in[18];
    const float* W2_s  = (const float*)d_in[19];
    const float* b2_s  = (const float*)d_in[20];

    const int E2 = in_sizes[1] / 2;
    const int E3 = in_sizes[2] / 3;
    const int ES = in_sizes[3] / 2;

    float* out = (float*)d_out;

    zero_kernel<<<(out_size + 255) / 256, 256>>>(out, out_size);

    constexpr int BLK = 128;
    const int B2 = (E2 + 2*NP3B * BLK - 1) / (2*NP3B * BLK);
    const int B3 = (E3 + 2*NP6B * BLK - 1) / (2*NP6B * BLK);
    const int BS = (ES + 2*NP3B * BLK - 1) / (2*NP3B * BLK);

    fused_hignn_kernel<<<B2 + B3 + BS, BLK>>>(
        x,
        e2, a2, W1_2b, b1_2b, W2_2b, b2_2b,
        e3, a3, W1_3b, b1_3b, W2_3b, b2_3b,
        es, as, W1_s, b1_s, W2_s, b2_s,
        out, E2, E3, ES, B2, B3, BS);
}

// round 13
// speedup vs baseline: 1.3493x; 1.3493x over previous
#include <cuda_runtime.h>

#define HID 64
typedef unsigned long long u64;

__device__ __forceinline__ u64 pk2(float lo, float hi) {
    u64 r; asm("mov.b64 %0, {%1,%2};" : "=l"(r) : "f"(lo), "f"(hi)); return r;
}
__device__ __forceinline__ void upk2(u64 v, float& lo, float& hi) {
    asm("mov.b64 {%0,%1}, %2;" : "=f"(lo), "=f"(hi) : "l"(v));
}
__device__ __forceinline__ u64 ffma2(u64 a, u64 b, u64 c) {
    u64 d; asm("fma.rn.f32x2 %0, %1, %2, %3;" : "=l"(d) : "l"(a), "l"(b), "l"(c)); return d;
}
__device__ __forceinline__ u64 fmul2(u64 a, u64 b) {
    u64 d; asm("mul.rn.f32x2 %0, %1, %2;" : "=l"(d) : "l"(a), "l"(b)); return d;
}

__global__ void zero_kernel(float* __restrict__ out, int n) {
    int i = blockIdx.x * blockDim.x + threadIdx.x;
    if (i < n) out[i] = 0.0f;
}

// R11 scheme (best): h-PAIR packed weights (16-u64 / 128B block per h2),
// attr folded into layer 2, 3 packed accumulators per edge.
// This round: higher EPT to amortize the smem crossbar cost (the measured
// binder), 4-block launch bound, deeper unroll for LDS/FMA pipelining.
template<int DIN, int EPT>
__device__ __forceinline__ void run_family(
    const float* __restrict__ x,
    const int*   __restrict__ edges,
    const float* __restrict__ attr,
    const float* __restrict__ W1, const float* __restrict__ b1,
    const float* __restrict__ W2, const float* __restrict__ b2,
    float* __restrict__ out, int E, int blk, int nblk, u64* smem)
{
    u64*   sWB = smem;                      // [16 * 32]
    float* sB2 = (float*)(sWB + 16 * 32);   // [9]

    for (int idx = threadIdx.x; idx < 16 * 32; idx += blockDim.x) {
        int h2 = idx >> 4, s = idx & 15;
        int h0 = 2 * h2, h1 = 2 * h2 + 1;
        float lo = 0.0f, hi = 0.0f;
        if (s < DIN)           { lo = W1[s * HID + h0]; hi = W1[s * HID + h1]; }
        else if (s == DIN)     { lo = b1[h0];           hi = b1[h1]; }
        else if (s <= DIN + 9) { int m = s - DIN - 1; lo = W2[h0 * 9 + m]; hi = W2[h1 * 9 + m]; }
        sWB[idx] = pk2(lo, hi);
    }
    if (threadIdx.x < 9) sB2[threadIdx.x] = b2[threadIdx.x];
    __syncthreads();

    const int tid    = blk * (int)blockDim.x + (int)threadIdx.x;
    const int stride = nblk * (int)blockDim.x;

    float dv[EPT][DIN];    // scalar MLP inputs
    u64   atd[EPT][3];     // (at_m, at_m) duplicated attrs
    u64   acc[EPT][3];     // packed y accumulators (even-h lane0, odd-h lane1)
    int   tgt[EPT];
    bool  valid[EPT];

    #pragma unroll
    for (int k = 0; k < EPT; k++) {
        int e = tid + k * stride;
        valid[k] = (e < E);
        int ee = valid[k] ? e : 0;
        int i;
        if (DIN == 3) {
            int j = edges[ee];
            i = edges[E + ee];
            dv[k][0] = x[3*j+0] - x[3*i+0];
            dv[k][1] = x[3*j+1] - x[3*i+1];
            dv[k][2] = x[3*j+2] - x[3*i+2];
        } else {
            int j  = edges[ee];
            int kk = edges[E + ee];
            i = edges[2*E + ee];
            float xk0 = x[3*kk+0], xk1 = x[3*kk+1], xk2 = x[3*kk+2];
            dv[k][0] = xk0 - x[3*j+0];
            dv[k][1] = xk1 - x[3*j+1];
            dv[k][2] = xk2 - x[3*j+2];
            dv[k][3] = x[3*i+0] - xk0;
            dv[k][4] = x[3*i+1] - xk1;
            dv[k][5] = x[3*i+2] - xk2;
        }
        tgt[k] = i;
        float a0 = attr[3*ee+0], a1 = attr[3*ee+1], a2v = attr[3*ee+2];
        atd[k][0] = pk2(a0, a0);
        atd[k][1] = pk2(a1, a1);
        atd[k][2] = pk2(a2v, a2v);
        // seed with b2 . attr (even-h lane)
        #pragma unroll
        for (int i2 = 0; i2 < 3; i2++) {
            float s0 = fmaf(sB2[3*i2+0], a0,
                       fmaf(sB2[3*i2+1], a1, sB2[3*i2+2] * a2v));
            acc[k][i2] = pk2(s0, 0.0f);
        }
    }

    // Mainloop: 32 h-pair iterations, 7 (DIN3) / 8 (DIN6) LDS.128 each.
    #pragma unroll 4
    for (int h2 = 0; h2 < 32; h2++) {
        const float4* w4 = (const float4*)(sWB + h2 * 16);
        u64 hv[EPT];
        u64 w2p[9];

        if (DIN == 3) {
            float4 qa = w4[0];                 // w1_0 pair, w1_1 pair
            float4 qb = w4[1];                 // w1_2 pair, b1 pair
            #pragma unroll
            for (int k = 0; k < EPT; k++) {
                float t0 = fmaf(dv[k][0], qa.x, qb.z);
                float t1 = fmaf(dv[k][0], qa.y, qb.w);
                t0 = fmaf(dv[k][1], qa.z, t0);
                t1 = fmaf(dv[k][1], qa.w, t1);
                t0 = fmaf(dv[k][2], qb.x, t0);
                t1 = fmaf(dv[k][2], qb.y, t1);
                hv[k] = pk2(fmaxf(t0, 0.0f), fmaxf(t1, 0.0f));
            }
            float4 q2 = w4[2], q3 = w4[3], q4 = w4[4], q5 = w4[5], q6 = w4[6];
            w2p[0] = pk2(q2.x, q2.y); w2p[1] = pk2(q2.z, q2.w);
            w2p[2] = pk2(q3.x, q3.y); w2p[3] = pk2(q3.z, q3.w);
            w2p[4] = pk2(q4.x, q4.y); w2p[5] = pk2(q4.z, q4.w);
            w2p[6] = pk2(q5.x, q5.y); w2p[7] = pk2(q5.z, q5.w);
            w2p[8] = pk2(q6.x, q6.y);
        } else {
            float4 qa = w4[0], qb = w4[1], qc = w4[2], qd = w4[3];
            #pragma unroll
            for (int k = 0; k < EPT; k++) {
                float t0 = fmaf(dv[k][0], qa.x, qd.x);
                float t1 = fmaf(dv[k][0], qa.y, qd.y);
                t0 = fmaf(dv[k][1], qa.z, t0);
                t1 = fmaf(dv[k][1], qa.w, t1);
                t0 = fmaf(dv[k][2], qb.x, t0);
                t1 = fmaf(dv[k][2], qb.y, t1);
                t0 = fmaf(dv[k][3], qb.z, t0);
                t1 = fmaf(dv[k][3], qb.w, t1);
                t0 = fmaf(dv[k][4], qc.x, t0);
                t1 = fmaf(dv[k][4], qc.y, t1);
                t0 = fmaf(dv[k][5], qc.z, t0);
                t1 = fmaf(dv[k][5], qc.w, t1);
                hv[k] = pk2(fmaxf(t0, 0.0f), fmaxf(t1, 0.0f));
            }
            float4 q4 = w4[4], q5 = w4[5], q6 = w4[6], q7 = w4[7];
            w2p[0] = pk2(qd.z, qd.w);
            w2p[1] = pk2(q4.x, q4.y); w2p[2] = pk2(q4.z, q4.w);
            w2p[3] = pk2(q5.x, q5.y); w2p[4] = pk2(q5.z, q5.w);
            w2p[5] = pk2(q6.x, q6.y); w2p[6] = pk2(q6.z, q6.w);
            w2p[7] = pk2(q7.x, q7.y); w2p[8] = pk2(q7.z, q7.w);
        }

        // Layer 2 with attr folded: tmp_i = sum_m w2p[3i+m] (.) atd_m ;
        // acc_i += hv (.) tmp_i
        #pragma unroll
        for (int k = 0; k < EPT; k++) {
            #pragma unroll
            for (int i = 0; i < 3; i++) {
                u64 t = fmul2(w2p[3*i+2], atd[k][2]);
                t = ffma2(w2p[3*i+1], atd[k][1], t);
                t = ffma2(w2p[3*i+0], atd[k][0], t);
                acc[k][i] = ffma2(hv[k], t, acc[k][i]);
            }
        }
    }

    // Epilogue: y_i = lane0 + lane1, scatter-add.
    #pragma unroll
    for (int k = 0; k < EPT; k++) {
        if (!valid[k]) continue;
        #pragma unroll
        for (int i = 0; i < 3; i++) {
            float lo, hi; upk2(acc[k][i], lo, hi);
            atomicAdd(&out[3*tgt[k] + i], lo + hi);
        }
    }
}

#define EPT3B 5   // DIN=3 families
#define EPT6B 4   // DIN=6 family

__global__ __launch_bounds__(128, 4)
void fused_hignn_kernel(
    const float* __restrict__ x,
    const int* __restrict__ e2, const float* __restrict__ a2,
    const float* __restrict__ W1_2b, const float* __restrict__ b1_2b,
    const float* __restrict__ W2_2b, const float* __restrict__ b2_2b,
    const int* __restrict__ e3, const float* __restrict__ a3,
    const float* __restrict__ W1_3b, const float* __restrict__ b1_3b,
    const float* __restrict__ W2_3b, const float* __restrict__ b2_3b,
    const int* __restrict__ es, const float* __restrict__ as,
    const float* __restrict__ W1_s, const float* __restrict__ b1_s,
    const float* __restrict__ W2_s, const float* __restrict__ b2_s,
    float* __restrict__ out,
    int E2, int E3, int ES, int B2, int B3, int BS)
{
    __shared__ __align__(16) u64 smem[16 * 32 + 8];
    int b = blockIdx.x;
    if (b < B2) {
        run_family<3, EPT3B>(x, e2, a2, W1_2b, b1_2b, W2_2b, b2_2b, out, E2, b, B2, smem);
    } else if (b < B2 + B3) {
        run_family<6, EPT6B>(x, e3, a3, W1_3b, b1_3b, W2_3b, b2_3b, out, E3, b - B2, B3, smem);
    } else {
        run_family<3, EPT3B>(x, es, as, W1_s, b1_s, W2_s, b2_s, out, ES, b - B2 - B3, BS, smem);
    }
}

extern "C" void kernel_launch(void* const* d_in, const int* in_sizes, int n_in,
                              void* d_out, int out_size)
{
    const float* x   = (const float*)d_in[0];
    const int*   e2  = (const int*)  d_in[1];
    const int*   e3  = (const int*)  d_in[2];
    const int*   es  = (const int*)  d_in[3];
    const float* a2  = (const float*)d_in[5];
    const float* a3  = (const float*)d_in[6];
    const float* as  = (const float*)d_in[7];
    const float* W1_2b = (const float*)d_in[9];
    const float* b1_2b = (const float*)d_in[10];
    const float* W2_2b = (const float*)d_in[11];
    const float* b2_2b = (const float*)d_in[12];
    const float* W1_3b = (const float*)d_in[13];
    const float* b1_3b = (const float*)d_in[14];
    const float* W2_3b = (const float*)d_in[15];
    const float* b2_3b = (const float*)d_in[16];
    const float* W1_s  = (const float*)d_in[17];
    const float* b1_s  = (const float*)d_in[18];
    const float* W2_s  = (const float*)d_in[19];
    const float* b2_s  = (const float*)d_in[20];

    const int E2 = in_sizes[1] / 2;
    const int E3 = in_sizes[2] / 3;
    const int ES = in_sizes[3] / 2;

    float* out = (float*)d_out;

    zero_kernel<<<(out_size + 255) / 256, 256>>>(out, out_size);

    constexpr int BLK = 128;
    const int B2 = (E2 + EPT3B * BLK - 1) / (EPT3B * BLK);
    const int B3 = (E3 + EPT6B * BLK - 1) / (EPT6B * BLK);
    const int BS = (ES + EPT3B * BLK - 1) / (EPT3B * BLK);

    fused_hignn_kernel<<<B2 + B3 + BS, BLK>>>(
        x,
        e2, a2, W1_2b, b1_2b, W2_2b, b2_2b,
        e3, a3, W1_3b, b1_3b, W2_3b, b2_3b,
        es, as, W1_s, b1_s, W2_s, b2_s,
        out, E2, E3, ES, B2, B3, BS);
}

// round 14
// speedup vs baseline: 1.3683x; 1.0141x over previous
#include <cuda_runtime.h>

#define HID 64
typedef unsigned long long u64;

__device__ __forceinline__ u64 pk2(float lo, float hi) {
    u64 r; asm("mov.b64 %0, {%1,%2};" : "=l"(r) : "f"(lo), "f"(hi)); return r;
}
__device__ __forceinline__ void upk2(u64 v, float& lo, float& hi) {
    asm("mov.b64 {%0,%1}, %2;" : "=f"(lo), "=f"(hi) : "l"(v));
}
__device__ __forceinline__ u64 ffma2(u64 a, u64 b, u64 c) {
    u64 d; asm("fma.rn.f32x2 %0, %1, %2, %3;" : "=l"(d) : "l"(a), "l"(b), "l"(c)); return d;
}
__device__ __forceinline__ u64 fmul2(u64 a, u64 b) {
    u64 d; asm("mul.rn.f32x2 %0, %1, %2;" : "=l"(d) : "l"(a), "l"(b)); return d;
}

__global__ void zero_kernel(float* __restrict__ out, int n) {
    int i = blockIdx.x * blockDim.x + threadIdx.x;
    if (i < n) out[i] = 0.0f;
}

// h-PAIR packed weights (16-u64 / 128B block per h2), attr folded into
// layer 2, 3 packed accumulators per edge (R13 scheme).
// This round: EPT 5->6 paid for by live-range engineering:
//  - layer-2 runs i-OUTER / k-INNER with only 3 W2 pairs live (LDS.64 direct
//    into u64, no staging array, no re-pack movs)
//  - valid[] recomputed in the epilogue instead of stored
template<int DIN, int EPT>
__device__ __forceinline__ void run_family(
    const float* __restrict__ x,
    const int*   __restrict__ edges,
    const float* __restrict__ attr,
    const float* __restrict__ W1, const float* __restrict__ b1,
    const float* __restrict__ W2, const float* __restrict__ b2,
    float* __restrict__ out, int E, int blk, int nblk, u64* smem)
{
    u64*   sWB = smem;                      // [16 * 32]
    float* sB2 = (float*)(sWB + 16 * 32);   // [9]

    for (int idx = threadIdx.x; idx < 16 * 32; idx += blockDim.x) {
        int h2 = idx >> 4, s = idx & 15;
        int h0 = 2 * h2, h1 = 2 * h2 + 1;
        float lo = 0.0f, hi = 0.0f;
        if (s < DIN)           { lo = W1[s * HID + h0]; hi = W1[s * HID + h1]; }
        else if (s == DIN)     { lo = b1[h0];           hi = b1[h1]; }
        else if (s <= DIN + 9) { int m = s - DIN - 1; lo = W2[h0 * 9 + m]; hi = W2[h1 * 9 + m]; }
        sWB[idx] = pk2(lo, hi);
    }
    if (threadIdx.x < 9) sB2[threadIdx.x] = b2[threadIdx.x];
    __syncthreads();

    const int tid    = blk * (int)blockDim.x + (int)threadIdx.x;
    const int stride = nblk * (int)blockDim.x;

    float dv[EPT][DIN];    // scalar MLP inputs
    u64   atd[EPT][3];     // (at_m, at_m) duplicated attrs
    u64   acc[EPT][3];     // packed y accumulators (even-h lane0, odd-h lane1)
    int   tgt[EPT];

    #pragma unroll
    for (int k = 0; k < EPT; k++) {
        int e = tid + k * stride;
        int ee = (e < E) ? e : 0;
        int i;
        if (DIN == 3) {
            int j = edges[ee];
            i = edges[E + ee];
            dv[k][0] = x[3*j+0] - x[3*i+0];
            dv[k][1] = x[3*j+1] - x[3*i+1];
            dv[k][2] = x[3*j+2] - x[3*i+2];
        } else {
            int j  = edges[ee];
            int kk = edges[E + ee];
            i = edges[2*E + ee];
            float xk0 = x[3*kk+0], xk1 = x[3*kk+1], xk2 = x[3*kk+2];
            dv[k][0] = xk0 - x[3*j+0];
            dv[k][1] = xk1 - x[3*j+1];
            dv[k][2] = xk2 - x[3*j+2];
            dv[k][3] = x[3*i+0] - xk0;
            dv[k][4] = x[3*i+1] - xk1;
            dv[k][5] = x[3*i+2] - xk2;
        }
        tgt[k] = i;
        float a0 = attr[3*ee+0], a1 = attr[3*ee+1], a2v = attr[3*ee+2];
        atd[k][0] = pk2(a0, a0);
        atd[k][1] = pk2(a1, a1);
        atd[k][2] = pk2(a2v, a2v);
        // seed with b2 . attr (even-h lane)
        #pragma unroll
        for (int i2 = 0; i2 < 3; i2++) {
            float s0 = fmaf(sB2[3*i2+0], a0,
                       fmaf(sB2[3*i2+1], a1, sB2[3*i2+2] * a2v));
            acc[k][i2] = pk2(s0, 0.0f);
        }
    }

    // Mainloop: 32 h-pair iterations.
    #pragma unroll 4
    for (int h2 = 0; h2 < 32; h2++) {
        const u64*    wp = sWB + h2 * 16;
        const float4* w4 = (const float4*)wp;
        u64 hv[EPT];

        if (DIN == 3) {
            float4 qa = w4[0];                 // w1_0 pair, w1_1 pair
            float4 qb = w4[1];                 // w1_2 pair, b1 pair
            #pragma unroll
            for (int k = 0; k < EPT; k++) {
                float t0 = fmaf(dv[k][0], qa.x, qb.z);
                float t1 = fmaf(dv[k][0], qa.y, qb.w);
                t0 = fmaf(dv[k][1], qa.z, t0);
                t1 = fmaf(dv[k][1], qa.w, t1);
                t0 = fmaf(dv[k][2], qb.x, t0);
                t1 = fmaf(dv[k][2], qb.y, t1);
                hv[k] = pk2(fmaxf(t0, 0.0f), fmaxf(t1, 0.0f));
            }
        } else {
            float4 qa = w4[0], qb = w4[1], qc = w4[2];
            float4 qd = w4[3];                 // b1 pair, w2_0 pair (w2_0 unused here)
            #pragma unroll
            for (int k = 0; k < EPT; k++) {
                float t0 = fmaf(dv[k][0], qa.x, qd.x);
                float t1 = fmaf(dv[k][0], qa.y, qd.y);
                t0 = fmaf(dv[k][1], qa.z, t0);
                t1 = fmaf(dv[k][1], qa.w, t1);
                t0 = fmaf(dv[k][2], qb.x, t0);
                t1 = fmaf(dv[k][2], qb.y, t1);
                t0 = fmaf(dv[k][3], qb.z, t0);
                t1 = fmaf(dv[k][3], qb.w, t1);
                t0 = fmaf(dv[k][4], qc.x, t0);
                t1 = fmaf(dv[k][4], qc.y, t1);
                t0 = fmaf(dv[k][5], qc.z, t0);
                t1 = fmaf(dv[k][5], qc.w, t1);
                hv[k] = pk2(fmaxf(t0, 0.0f), fmaxf(t1, 0.0f));
            }
        }

        // Layer 2, i-outer / k-inner: only 3 W2 pairs live at a time,
        // loaded directly as u64 (LDS.64, no packing movs).
        #pragma unroll
        for (int i = 0; i < 3; i++) {
            u64 w0 = wp[DIN + 1 + 3*i + 0];
            u64 w1 = wp[DIN + 1 + 3*i + 1];
            u64 w2 = wp[DIN + 1 + 3*i + 2];
            #pragma unroll
            for (int k = 0; k < EPT; k++) {
                u64 t = fmul2(w2, atd[k][2]);
                t = ffma2(w1, atd[k][1], t);
                t = ffma2(w0, atd[k][0], t);
                acc[k][i] = ffma2(hv[k], t, acc[k][i]);
            }
        }
    }

    // Epilogue: y_i = lane0 + lane1, scatter-add (valid recomputed).
    #pragma unroll
    for (int k = 0; k < EPT; k++) {
        if (tid + k * stride < E) {
            #pragma unroll
            for (int i = 0; i < 3; i++) {
                float lo, hi; upk2(acc[k][i], lo, hi);
                atomicAdd(&out[3*tgt[k] + i], lo + hi);
            }
        }
    }
}

#define EPT3B 6   // DIN=3 families
#define EPT6B 4   // DIN=6 family

__global__ __launch_bounds__(128, 4)
void fused_hignn_kernel(
    const float* __restrict__ x,
    const int* __restrict__ e2, const float* __restrict__ a2,
    const float* __restrict__ W1_2b, const float* __restrict__ b1_2b,
    const float* __restrict__ W2_2b, const float* __restrict__ b2_2b,
    const int* __restrict__ e3, const float* __restrict__ a3,
    const float* __restrict__ W1_3b, const float* __restrict__ b1_3b,
    const float* __restrict__ W2_3b, const float* __restrict__ b2_3b,
    const int* __restrict__ es, const float* __restrict__ as,
    const float* __restrict__ W1_s, const float* __restrict__ b1_s,
    const float* __restrict__ W2_s, const float* __restrict__ b2_s,
    float* __restrict__ out,
    int E2, int E3, int ES, int B2, int B3, int BS)
{
    __shared__ __align__(16) u64 smem[16 * 32 + 8];
    int b = blockIdx.x;
    if (b < B2) {
        run_family<3, EPT3B>(x, e2, a2, W1_2b, b1_2b, W2_2b, b2_2b, out, E2, b, B2, smem);
    } else if (b < B2 + B3) {
        run_family<6, EPT6B>(x, e3, a3, W1_3b, b1_3b, W2_3b, b2_3b, out, E3, b - B2, B3, smem);
    } else {
        run_family<3, EPT3B>(x, es, as, W1_s, b1_s, W2_s, b2_s, out, ES, b - B2 - B3, BS, smem);
    }
}

extern "C" void kernel_launch(void* const* d_in, const int* in_sizes, int n_in,
                              void* d_out, int out_size)
{
    const float* x   = (const float*)d_in[0];
    const int*   e2  = (const int*)  d_in[1];
    const int*   e3  = (const int*)  d_in[2];
    const int*   es  = (const int*)  d_in[3];
    const float* a2  = (const float*)d_in[5];
    const float* a3  = (const float*)d_in[6];
    const float* as  = (const float*)d_in[7];
    const float* W1_2b = (const float*)d_in[9];
    const float* b1_2b = (const float*)d_in[10];
    const float* W2_2b = (const float*)d_in[11];
    const float* b2_2b = (const float*)d_in[12];
    const float* W1_3b = (const float*)d_in[13];
    const float* b1_3b = (const float*)d_in[14];
    const float* W2_3b = (const float*)d_in[15];
    const float* b2_3b = (const float*)d_in[16];
    const float* W1_s  = (const float*)d_in[17];
    const float* b1_s  = (const float*)d_in[18];
    const float* W2_s  = (const float*)d_in[19];
    const float* b2_s  = (const float*)d_in[20];

    const int E2 = in_sizes[1] / 2;
    const int E3 = in_sizes[2] / 3;
    const int ES = in_sizes[3] / 2;

    float* out = (float*)d_out;

    zero_kernel<<<(out_size + 255) / 256, 256>>>(out, out_size);

    constexpr int BLK = 128;
    const int B2 = (E2 + EPT3B * BLK - 1) / (EPT3B * BLK);
    const int B3 = (E3 + EPT6B * BLK - 1) / (EPT6B * BLK);
    const int BS = (ES + EPT3B * BLK - 1) / (EPT3B * BLK);

    fused_hignn_kernel<<<B2 + B3 + BS, BLK>>>(
        x,
        e2, a2, W1_2b, b1_2b, W2_2b, b2_2b,
        e3, a3, W1_3b, b1_3b, W2_3b, b2_3b,
        es, as, W1_s, b1_s, W2_s, b2_s,
        out, E2, E3, ES, B2, B3, BS);
}